// round 14
// baseline (speedup 1.0000x reference)
#include <cuda_runtime.h>
#include <math.h>
#include <stdint.h>

#define B_DIM 32
#define T_SEQ 512
#define D_DIM 512
#define U_DIM 512
#define NG    2048                 // 4*U
#define M_TOT (B_DIM * T_SEQ)     // 16384

// ---------------- scratch (static device memory; no allocations) ----------------
__device__ float g_hbuf[2][2][B_DIM][U_DIM];       // h double buffers (k-PERMUTED, tf32-rounded)
__device__ float g_hb_out[B_DIM][T_SEQ][U_DIM];    // backward-direction outputs
__device__ float g_xP[M_TOT][D_DIM];               // tf32 x, k-PERMUTED within 8-blocks (32 MB)

// Chunked barrier state (see R8/R9): chunk c = producer CTAs blk 16c..16c+15 = k-range
// [128c,128c+128). Padded lines, monotonic across graph replays.
__device__ unsigned g_chcnt[2][4][32];             // [dir][chunk][pad] arrival counters
__device__ volatile unsigned g_chep[2][4][32];     // [dir][chunk][pad] chunk epochs

#define NCTA_DIR    64
#define REC_THREADS 256

// ---------------- tf32 helpers ----------------
__device__ __forceinline__ unsigned f2tf32(float f)
{
    unsigned r;
    asm("cvt.rna.tf32.f32 %0, %1;" : "=r"(r) : "f"(f));
    return r;
}
__device__ __forceinline__ float tf32f(float f) { return __uint_as_float(f2tf32(f)); }

// D += A@B, m16n8k8, A row-major, B col-major, tf32 in / fp32 accum
__device__ __forceinline__ void mma8(float* c,
                                     unsigned a0, unsigned a1, unsigned a2, unsigned a3,
                                     unsigned b0, unsigned b1)
{
    asm("mma.sync.aligned.m16n8k8.row.col.f32.tf32.tf32.f32 "
        "{%0,%1,%2,%3},{%4,%5,%6,%7},{%8,%9},{%0,%1,%2,%3};"
        : "+f"(c[0]), "+f"(c[1]), "+f"(c[2]), "+f"(c[3])
        : "r"(a0), "r"(a1), "r"(a2), "r"(a3), "r"(b0), "r"(b1));
}

// k-permutation within each 8-block: (pi(k),pi(k)+1) consecutive = (k, k+4)
__device__ __forceinline__ int perm8(int k)
{
    return (k & ~7) | ((k & 3) << 1) | ((k & 7) >> 2);
}

// ---------------- fast transcendentals (MUFU-based, saturation-safe) ----------------
__device__ __forceinline__ float fsigm(float x)
{
    return __fdividef(1.0f, 1.0f + __expf(-x));
}
__device__ __forceinline__ float ftanh(float x)
{
    return 1.0f - __fdividef(2.0f, 1.0f + __expf(2.0f * x));
}

// ---------------- release/acquire barrier primitives (no full MEMBAR) ----------------
__device__ __forceinline__ void ch_arrive(int dir, int chunk, unsigned ep_next)
{
    unsigned v;
    asm volatile("atom.add.release.gpu.u32 %0, [%1], %2;"
                 : "=r"(v)
                 : "l"((unsigned*)&g_chcnt[dir][chunk][0]), "r"(1u)
                 : "memory");
    if ((v & 15u) == 15u)
        asm volatile("st.release.gpu.u32 [%0], %1;"
                     :: "l"((unsigned*)&g_chep[dir][chunk][0]), "r"(ep_next)
                     : "memory");
}

__device__ __forceinline__ void ch_wait(int dir, int ck, unsigned ep0, unsigned need)
{
    unsigned cur;
    do {
        asm volatile("ld.acquire.gpu.u32 %0, [%1];"
                     : "=r"(cur)
                     : "l"((const unsigned*)&g_chep[dir][ck][0])
                     : "memory");
    } while (cur - ep0 < need);
}

// =================================================================================
// Pre-pass: g_xP[m][perm8(k)] = tf32(x[m][k])  — pure column permute
// =================================================================================
__global__ void cvt_xP(const float* __restrict__ X)
{
    int t = blockIdx.x * blockDim.x + threadIdx.x;   // one 8-block per thread
    if (t < M_TOT * D_DIM / 8) {
        const float* src = X + (size_t)t * 8;
        float4 lo = *(const float4*)src;             // k0..k3
        float4 hi = *(const float4*)(src + 4);       // k4..k7
        float4 o0, o1;                               // positions 0..3, 4..7
        o0.x = tf32f(lo.x); o0.y = tf32f(hi.x); o0.z = tf32f(lo.y); o0.w = tf32f(hi.y);
        o1.x = tf32f(lo.z); o1.y = tf32f(hi.z); o1.z = tf32f(lo.w); o1.w = tf32f(hi.w);
        float* dst = &g_xP[0][0] + (size_t)t * 8;
        *(float4*)dst       = o0;
        *(float4*)(dst + 4) = o1;
    }
}

// =================================================================================
// Fused persistent bidirectional LSTM — tf32 tensor cores, xg GEMM folded in.
// 128 CTAs (64/dir, dir=bid&1), 256 threads (8 warps), CTA owns 8 units
// (= 32 gate-cols of BOTH U and W). NEW vs R12: x(s+1) is PREFETCHED at the end
// of step s (after the gp-publish __syncthreads, when no thread reads hs until
// the next xg mma), so its cp.async latency hides under epilogue + arrival +
// producer spread instead of sitting at the top of the step.
// =================================================================================
#define US_STR 520
#define GP_STR 34
#define SMEM_REC ((3 * 32 * US_STR + 2 * 32 * GP_STR + 32) * 4)   // 208,512 B

__global__ __launch_bounds__(REC_THREADS, 1) void lstm_rec(
    const float* __restrict__ z,
    const float* __restrict__ Uf, const float* __restrict__ Ub,
    const float* __restrict__ Wf, const float* __restrict__ Wb,
    const float* __restrict__ bf, const float* __restrict__ bb,
    float* __restrict__ out)
{
    extern __shared__ float sm[];
    float* Us = sm;                       // [32 local cols][US_STR] (U slice, k-perm tf32)
    float* Ws = sm + 32 * US_STR;         // [32 local cols][US_STR] (W slice, k-perm tf32)
    float* hs = sm + 64 * US_STR;         // [32 batches][US_STR]   (x then h staging)
    float* gp = sm + 96 * US_STR;         // [2 khalf][32 batches][GP_STR] partial preacts
    float* bs = sm + 96 * US_STR + 2 * 32 * GP_STR;   // [32] bias slice

    const int bid = blockIdx.x;
    const int dir = bid & 1;
    const int blk = bid >> 1;             // 0..63
    const int chunk = blk >> 4;           // 0..3 (this CTA's producer chunk)
    const int u0  = blk * 8;
    const int tid = threadIdx.x;
    const int lane = tid & 31, wid = tid >> 5;
    const int gid = lane >> 2, tig = lane & 3;
    const int mhalf = wid & 1;
    const int gpair = (wid >> 1) & 1;
    const int khalf = wid >> 2;           // threads 0-127: 0, 128-255: 1
    const int g0 = gpair * 2, g1 = g0 + 1;
    const int r0 = mhalf * 16 + gid;
    const int lt = tid & 127;             // index within K-half group
    const float* __restrict__ Uw = dir ? Ub : Uf;
    const float* __restrict__ Ww = dir ? Wb : Wf;
    const float* __restrict__ bias = dir ? bb : bf;

    // Epoch base: own chunk's word (race-free pre-arrival read; all words equal
    // at every replay start).
    const unsigned ep0 = g_chep[dir][chunk][0];

    // ---- load U and W slices into smem: [localcol][perm8(k)] (tf32) ----
    {
        int ci = tid & 31;                // local col: gate(ci>>3) x unit(ci&7)
        int kc = tid >> 5;                // k chunk (0..7), 64 k each
        int g  = ci >> 3, uul = ci & 7;
        size_t coloff = (size_t)(g * U_DIM + u0 + uul);
        const float* srcU = Uw + coloff;
        const float* srcW = Ww + coloff;
        float* dstU = Us + ci * US_STR;
        float* dstW = Ws + ci * US_STR;
        for (int k = kc * 64; k < kc * 64 + 64; k++) {
            int p = perm8(k);
            dstU[p] = tf32f(srcU[(size_t)k * NG]);
            dstW[p] = tf32f(srcW[(size_t)k * NG]);
        }
        if (tid < 32) bs[tid] = bias[(tid >> 3) * U_DIM + u0 + (tid & 7)];
    }

    // ---- init state: h0 = c0 = z; h stored k-PERMUTED + tf32-rounded ----
    float cst;
    {
        int b = tid >> 3, uu = tid & 7;
        float zv = z[b * U_DIM + u0 + uu];
        cst = zv;
        g_hbuf[dir][0][b][u0 + ((uu & 3) << 1) + (uu >> 2)] = tf32f(zv);
    }
    __syncthreads();
    if (tid == 0) ch_arrive(dir, chunk, ep0 + 1u);

    const float* hrow0 = hs + r0 * US_STR;
    const float* hrow1 = hs + (r0 + 8) * US_STR;
    const float* urow0 = Us + (g0 * 8 + gid) * US_STR;
    const float* urow1 = Us + (g1 * 8 + gid) * US_STR;
    const float* wrow0 = Ws + (g0 * 8 + gid) * US_STR;
    const float* wrow1 = Ws + (g1 * 8 + gid) * US_STR;
    float* gpb = gp + khalf * 32 * GP_STR;
    const float* xPbase = &g_xP[0][0];
    const unsigned hs_s = (unsigned)__cvta_generic_to_shared(hs);
    const int eb = tid >> 3, euu = tid & 7;           // epilogue (batch, unit)

    // x-tile staging for timestep tt (this khalf's 256 k, all 32 batches, 32 KB)
    auto stage_x = [&](int tt) {
        #pragma unroll
        for (int j = 0; j < 16; j++) {
            int idx = j * 128 + lt;               // 0..2047
            int b   = idx >> 6;                   // 64 x 16B chunks per batch
            int k   = khalf * 256 + (idx & 63) * 4;
            const float* src = xPbase + ((size_t)(b * T_SEQ + tt)) * D_DIM + k;
            unsigned dst = hs_s + (unsigned)(b * US_STR + k) * 4u;
            asm volatile("cp.async.cg.shared.global [%0], [%1], 16;" :: "r"(dst), "l"(src));
        }
        asm volatile("cp.async.commit_group;");
    };

    // prologue: prefetch x for step 0
    stage_x(dir ? (T_SEQ - 1) : 0);

    for (int s = 0; s < T_SEQ; s++) {
        const int buf = s & 1;
        const int tt  = dir ? (T_SEQ - 1 - s) : s;

        // x(tt) was prefetched in the previous step (or prologue): just join
        asm volatile("cp.async.wait_group 0;");
        asm volatile("bar.sync %0, 128;" :: "r"(1 + khalf));

        float c0f[4] = {0, 0, 0, 0}, c1f[4] = {0, 0, 0, 0};

        // xg mma: x(tt) @ W slice over this khalf's 256 k (fills the h wait)
        #pragma unroll 4
        for (int kb = 0; kb < 32; kb++) {
            int o = khalf * 256 + kb * 8 + 2 * tig;
            uint2 ar0 = *(const uint2*)(hrow0 + o);
            uint2 ar1 = *(const uint2*)(hrow1 + o);
            uint2 bw0 = *(const uint2*)(wrow0 + o);
            uint2 bw1 = *(const uint2*)(wrow1 + o);
            mma8(c0f, ar0.x, ar1.x, ar0.y, ar1.y, bw0.x, bw0.y);
            mma8(c1f, ar0.x, ar1.x, ar0.y, ar1.y, bw1.x, bw1.y);
        }

        // chunk-wise h: wait for each 128-k chunk's 16 producers, then stage.
        // The poll-barrier also orders all xg-mma shared reads before h overwrites.
        const float* hsrcBase = &g_hbuf[dir][buf][0][0];
        #pragma unroll
        for (int q = 0; q < 2; q++) {
            const int ck = khalf * 2 + q;
            if (lt == 0) ch_wait(dir, ck, ep0, 1u + (unsigned)s);
            asm volatile("bar.sync %0, 128;" :: "r"(1 + khalf));
            const int kq = khalf * 256 + q * 128;
            #pragma unroll
            for (int j = 0; j < 8; j++) {
                int idx = j * 128 + lt;           // 0..1023
                int b   = idx >> 5;
                int k   = kq + (idx & 31) * 4;
                const float* src = hsrcBase + b * U_DIM + k;
                unsigned dst = hs_s + (unsigned)(b * US_STR + k) * 4u;
                asm volatile("cp.async.cg.shared.global [%0], [%1], 16;" :: "r"(dst), "l"(src));
            }
            asm volatile("cp.async.commit_group;");
        }

        // h mma, same accumulators. sub-chunk 0 ready -> kb 0..15
        asm volatile("cp.async.wait_group 1;");
        asm volatile("bar.sync %0, 128;" :: "r"(1 + khalf));
        #pragma unroll 4
        for (int kb = 0; kb < 16; kb++) {
            int o = khalf * 256 + kb * 8 + 2 * tig;
            uint2 ar0 = *(const uint2*)(hrow0 + o);
            uint2 ar1 = *(const uint2*)(hrow1 + o);
            uint2 bu0 = *(const uint2*)(urow0 + o);
            uint2 bu1 = *(const uint2*)(urow1 + o);
            mma8(c0f, ar0.x, ar1.x, ar0.y, ar1.y, bu0.x, bu0.y);
            mma8(c1f, ar0.x, ar1.x, ar0.y, ar1.y, bu1.x, bu1.y);
        }
        // sub-chunk 1 ready -> kb 16..31
        asm volatile("cp.async.wait_group 0;");
        asm volatile("bar.sync %0, 128;" :: "r"(1 + khalf));
        #pragma unroll 4
        for (int kb = 16; kb < 32; kb++) {
            int o = khalf * 256 + kb * 8 + 2 * tig;
            uint2 ar0 = *(const uint2*)(hrow0 + o);
            uint2 ar1 = *(const uint2*)(hrow1 + o);
            uint2 bu0 = *(const uint2*)(urow0 + o);
            uint2 bu1 = *(const uint2*)(urow1 + o);
            mma8(c0f, ar0.x, ar1.x, ar0.y, ar1.y, bu0.x, bu0.y);
            mma8(c1f, ar0.x, ar1.x, ar0.y, ar1.y, bu1.x, bu1.y);
        }

        // publish partial preactivations (xg + h, this K-half)
        *(float2*)&gpb[r0 * GP_STR + g0 * 8 + 2 * tig]       = make_float2(c0f[0], c0f[1]);
        *(float2*)&gpb[(r0 + 8) * GP_STR + g0 * 8 + 2 * tig] = make_float2(c0f[2], c0f[3]);
        *(float2*)&gpb[r0 * GP_STR + g1 * 8 + 2 * tig]       = make_float2(c1f[0], c1f[1]);
        *(float2*)&gpb[(r0 + 8) * GP_STR + g1 * 8 + 2 * tig] = make_float2(c1f[2], c1f[3]);
        __syncthreads();   // after this, NO thread reads hs until next step's xg mma

        // prefetch x for step s+1 — latency hides under epilogue + arrival +
        // producer spread (hs is not read again before next step's wait_group)
        if (s + 1 < T_SEQ)
            stage_x(dir ? (T_SEQ - 2 - s) : (s + 1));

        // epilogue: reduce K-halves + bias, gates (i,f,c,o), update, publish h FIRST
        float hv;
        {
            const float* p0 = gp + eb * GP_STR;
            const float* p1 = gp + (32 + eb) * GP_STR;
            float iv = fsigm(bs[euu]      + p0[euu]      + p1[euu]);
            float fv = fsigm(bs[8 + euu]  + p0[8 + euu]  + p1[8 + euu]);
            float cc = ftanh(bs[16 + euu] + p0[16 + euu] + p1[16 + euu]);
            float ov = fsigm(bs[24 + euu] + p0[24 + euu] + p1[24 + euu]);
            cst = fv * cst + iv * cc;
            hv = ov * ftanh(cst);
            g_hbuf[dir][buf ^ 1][eb][u0 + ((euu & 3) << 1) + (euu >> 2)] = tf32f(hv);
        }
        __syncthreads();

        // arrive (release our slice of h(s+1)) BEFORE output stores
        if (tid == 0) ch_arrive(dir, chunk, ep0 + 2u + (unsigned)s);

        if (dir == 0)
            out[((size_t)eb * T_SEQ + s) * U_DIM + u0 + euu] = hv;
        else
            g_hb_out[eb][tt][u0 + euu] = hv;
    }
}

// =================================================================================
// Kernel C: out += backward outputs
// =================================================================================
__global__ void add_bwd(float* __restrict__ out)
{
    int i = blockIdx.x * blockDim.x + threadIdx.x;
    const int n4 = B_DIM * T_SEQ * U_DIM / 4;
    if (i < n4) {
        float4 a = ((float4*)out)[i];
        float4 b = ((const float4*)&g_hb_out[0][0][0])[i];
        a.x += b.x; a.y += b.y; a.z += b.z; a.w += b.w;
        ((float4*)out)[i] = a;
    }
}

// =================================================================================
extern "C" void kernel_launch(void* const* d_in, const int* in_sizes, int n_in,
                              void* d_out, int out_size)
{
    const float* x  = (const float*)d_in[0];
    const float* z  = (const float*)d_in[1];
    const float* Wf = (const float*)d_in[2];
    const float* Uf = (const float*)d_in[3];
    const float* bf = (const float*)d_in[4];
    const float* Wb = (const float*)d_in[5];
    const float* Ub = (const float*)d_in[6];
    const float* bb = (const float*)d_in[7];
    float* out = (float*)d_out;

    cudaFuncSetAttribute(lstm_rec, cudaFuncAttributeMaxDynamicSharedMemorySize, SMEM_REC);

    // pre-pass: tf32-rounded, k-permuted x
    {
        int nblk = (M_TOT * D_DIM / 8 + 255) / 256;
        cvt_xP<<<nblk, 256>>>(x);
    }

    lstm_rec<<<2 * NCTA_DIR, REC_THREADS, SMEM_REC>>>(z, Uf, Ub, Wf, Wb, bf, bb, out);
    add_bwd<<<(B_DIM * T_SEQ * U_DIM / 4 + 255) / 256, 256>>>(out);
}